// round 2
// baseline (speedup 1.0000x reference)
#include <cuda_runtime.h>

// Problem dims
#define T_STEPS 64
#define B_DIM   32
#define W_DIM   1024
#define L_DIM   4
#define G_DIM   4096   // 4*W

// Launch config: 128 CTAs (<= 148 SMs -> all co-resident), 256 threads
#define NB 128
#define NT 256

// Scratch state (double-buffered h by step parity; c is owner-exclusive, single buffer)
__device__ float g_h[2][L_DIM][B_DIM][W_DIM];   // 1 MB
__device__ float g_c[L_DIM][B_DIM][W_DIM];      // 512 KB
__device__ unsigned int g_count = 0;
__device__ unsigned int g_gen   = 0;
__device__ int g_rmode = 0;   // 0=bool(1B), 1=int32, 2=float32

__device__ __forceinline__ void gridBarrier() {
    __syncthreads();
    if (threadIdx.x == 0) {
        volatile unsigned int* genp = &g_gen;
        unsigned int my = *genp;
        __threadfence();
        unsigned int arrived = atomicAdd(&g_count, 1);
        if (arrived == NB - 1) {
            atomicExch(&g_count, 0);
            __threadfence();
            *genp = my + 1;
        } else {
            while (*genp == my) { }
        }
        __threadfence();
    }
    __syncthreads();
}

__global__ __launch_bounds__(NT) void lstm_persistent_kernel(
    const float* __restrict__ x,          // (T,B,W)
    const void*  __restrict__ resets_raw, // (T,B) bool/int32/float32
    const float* __restrict__ c0,         // (L,B,W)
    const float* __restrict__ h0,         // (L,B,W)
    const float* __restrict__ Wx,         // (L,W,4W)
    const float* __restrict__ Wh,         // (L,W,4W)
    const float* __restrict__ bias,       // (L,4W)
    float* __restrict__ out)              // ys | cs_f | hs_f
{
    const int tid = threadIdx.x;
    const int cta = blockIdx.x;

    float* out_ys = out;                                   // T*B*W
    float* out_cs = out + (size_t)T_STEPS * B_DIM * W_DIM; // L*B*W
    float* out_hs = out_cs + (size_t)L_DIM * B_DIM * W_DIM;

    // ---------------- init phase ----------------
    // copy initial states into scratch (parity 0)
    {
        float* hflat = &g_h[0][0][0][0];
        float* cflat = &g_c[0][0][0];
        for (int i = cta * NT + tid; i < L_DIM * B_DIM * W_DIM; i += NB * NT) {
            hflat[i] = h0[i];
            cflat[i] = c0[i];
        }
    }
    // sniff resets dtype (byte-pattern test on first 2048 bytes, safe for all 3 dtypes)
    if (cta == 0 && tid == 0) {
        const unsigned char* rb = (const unsigned char*)resets_raw;
        int s1 = 0, s2 = 0, s3 = 0;
        for (int i = 0; i < T_STEPS * B_DIM; i += 4) {
            s1 += rb[i + 1]; s2 += rb[i + 2]; s3 += rb[i + 3];
        }
        g_rmode = (s1 > 0) ? 0 : ((s2 == 0 && s3 == 0) ? 1 : 2);
    }
    gridBarrier();
    const int rmode = g_rmode;

    // ---------------- shared memory ----------------
    // k-chunk staging of activations, transposed [k][b] with pad 4 (stride 36 keeps
    // float4 alignment and kills inner-loop conflicts; warp reads are broadcast anyway)
    __shared__ float ysm[128 * 36];
    __shared__ float hsm[128 * 36];
    __shared__ float gbuf[32 * 36];   // gate exchange: [col][b]
    __shared__ float mask_s[B_DIM];

    // ---------------- per-thread GEMM mapping ----------------
    // CTA owns 8 units u in [cta*8, cta*8+8) -> 32 gate columns (4 gates x 8 units)
    const int col  = tid & 31;        // 0..31 within CTA's column set
    const int bq   = tid >> 5;        // 0..7 -> batches 4*bq..4*bq+3
    const int gsel = col >> 3;        // gate index 0..3 (i,f,g,o)
    const int jj   = col & 7;
    const int u0   = cta * 8;
    const int ncol = gsel * W_DIM + (u0 + jj);   // column in 4096-wide gate matrix

    // update-stage mapping: one thread per (unit, batch)
    const int uu_up = tid & 7;
    const int b_up  = tid >> 3;       // 0..31

    // ---------------- time loop ----------------
    for (int t = 0; t < T_STEPS; ++t) {
        const int pOld = t & 1;
        const int pNew = pOld ^ 1;

        if (tid < B_DIM) {
            int rv;
            if (rmode == 0)      rv = ((const unsigned char*)resets_raw)[t * B_DIM + tid];
            else if (rmode == 1) rv = ((const int*)resets_raw)[t * B_DIM + tid];
            else                 rv = (((const float*)resets_raw)[t * B_DIM + tid] != 0.0f);
            mask_s[tid] = rv ? 0.0f : 1.0f;
        }
        // mask_s consumed after the __syncthreads() at the top of the first k-chunk

        for (int l = 0; l < L_DIM; ++l) {
            const float* y    = (l == 0) ? (x + (size_t)t * B_DIM * W_DIM)
                                         : &g_h[pNew][l - 1][0][0];
            const float* hOld = &g_h[pOld][l][0][0];
            const float* wx   = Wx + (size_t)l * W_DIM * G_DIM;
            const float* wh   = Wh + (size_t)l * W_DIM * G_DIM;

            float a0 = bias[l * G_DIM + ncol];
            float a1 = a0, a2 = a0, a3 = a0;

            for (int kc = 0; kc < W_DIM; kc += 128) {
                __syncthreads();   // protect smem reuse (and mask_s on first chunk)
                for (int idx = tid; idx < 128 * 32; idx += NT) {
                    int kk = idx & 127, bb = idx >> 7;
                    ysm[kk * 36 + bb] = y[bb * W_DIM + kc + kk];
                    hsm[kk * 36 + bb] = mask_s[bb] * hOld[bb * W_DIM + kc + kk];
                }
                __syncthreads();
                const float* wxp = wx + (size_t)kc * G_DIM + ncol;
                const float* whp = wh + (size_t)kc * G_DIM + ncol;
                #pragma unroll 8
                for (int kk = 0; kk < 128; ++kk) {
                    float wv = wxp[(size_t)kk * G_DIM];
                    float4 yv = *(const float4*)&ysm[kk * 36 + 4 * bq];
                    a0 = fmaf(yv.x, wv, a0); a1 = fmaf(yv.y, wv, a1);
                    a2 = fmaf(yv.z, wv, a2); a3 = fmaf(yv.w, wv, a3);
                    float wv2 = whp[(size_t)kk * G_DIM];
                    float4 hv = *(const float4*)&hsm[kk * 36 + 4 * bq];
                    a0 = fmaf(hv.x, wv2, a0); a1 = fmaf(hv.y, wv2, a1);
                    a2 = fmaf(hv.z, wv2, a2); a3 = fmaf(hv.w, wv2, a3);
                }
            }

            // exchange gates through smem so each (b,u) update is single-thread
            __syncthreads();
            gbuf[col * 36 + 4 * bq + 0] = a0;
            gbuf[col * 36 + 4 * bq + 1] = a1;
            gbuf[col * 36 + 4 * bq + 2] = a2;
            gbuf[col * 36 + 4 * bq + 3] = a3;
            __syncthreads();

            {
                float gi = gbuf[(0 * 8 + uu_up) * 36 + b_up];
                float gf = gbuf[(1 * 8 + uu_up) * 36 + b_up];
                float gg = gbuf[(2 * 8 + uu_up) * 36 + b_up];
                float go = gbuf[(3 * 8 + uu_up) * 36 + b_up];
                int u = u0 + uu_up;

                float cOld = mask_s[b_up] * g_c[l][b_up][u];
                float si = 1.0f / (1.0f + expf(-gi));
                float sf = 1.0f / (1.0f + expf(-gf));
                float so = 1.0f / (1.0f + expf(-go));
                float cNew = sf * cOld + si * tanhf(gg);
                float hNew = so * tanhf(cNew);

                g_c[l][b_up][u] = cNew;
                g_h[pNew][l][b_up][u] = hNew;
                if (l == L_DIM - 1)
                    out_ys[((size_t)t * B_DIM + b_up) * W_DIM + u] = hNew;
                if (t == T_STEPS - 1) {
                    out_cs[((size_t)l * B_DIM + b_up) * W_DIM + u] = cNew;
                    out_hs[((size_t)l * B_DIM + b_up) * W_DIM + u] = hNew;
                }
            }
            gridBarrier();   // h_new[l] now visible chip-wide for next phase
        }
    }
}

extern "C" void kernel_launch(void* const* d_in, const int* in_sizes, int n_in,
                              void* d_out, int out_size) {
    const float* x      = (const float*)d_in[0];
    const void*  resets = (const void*) d_in[1];
    const float* c0     = (const float*)d_in[2];
    const float* h0     = (const float*)d_in[3];
    const float* Wx     = (const float*)d_in[4];
    const float* Wh     = (const float*)d_in[5];
    const float* b      = (const float*)d_in[6];
    (void)in_sizes; (void)n_in; (void)out_size;

    lstm_persistent_kernel<<<NB, NT>>>(x, resets, c0, h0, Wx, Wh, b, (float*)d_out);
}

// round 3
// speedup vs baseline: 2.5128x; 2.5128x over previous
#include <cuda_runtime.h>

#define T_STEPS 64
#define B_DIM   32
#define W_DIM   1024
#define L_DIM   4
#define G_DIM   4096
#define NB      128
#define NT      256
#define KC      32          // k-chunk
#define NCHUNK  64          // 2048 / KC

typedef unsigned long long ull;

__device__ float g_h[2][L_DIM][B_DIM][W_DIM];
__device__ float g_c[L_DIM][B_DIM][W_DIM];
__device__ unsigned int g_count = 0;
__device__ unsigned int g_gen   = 0;
__device__ int g_rmode = 0;

__device__ __forceinline__ void gridBarrier() {
    __syncthreads();
    if (threadIdx.x == 0) {
        volatile unsigned int* genp = &g_gen;
        unsigned int my = *genp;
        __threadfence();
        unsigned int arrived = atomicAdd(&g_count, 1);
        if (arrived == NB - 1) {
            atomicExch(&g_count, 0);
            __threadfence();
            *genp = my + 1;
        } else {
            while (*genp == my) { }
        }
        __threadfence();
    }
    __syncthreads();
}

#define FFMA2(d, a, b) asm volatile("fma.rn.f32x2 %0, %1, %2, %0;" : "+l"(d) : "l"(a), "l"(b))
#define FADD2(d, a, b) asm volatile("add.rn.f32x2 %0, %1, %2;" : "=l"(d) : "l"(a), "l"(b))

__global__ __launch_bounds__(NT) void lstm_persistent_kernel(
    const float* __restrict__ x,
    const void*  __restrict__ resets_raw,
    const float* __restrict__ c0,
    const float* __restrict__ h0,
    const float* __restrict__ Wx,
    const float* __restrict__ Wh,
    const float* __restrict__ bias,
    float* __restrict__ out)
{
    const int tid = threadIdx.x;
    const int cta = blockIdx.x;

    float* out_ys = out;
    float* out_cs = out + (size_t)T_STEPS * B_DIM * W_DIM;
    float* out_hs = out_cs + (size_t)L_DIM * B_DIM * W_DIM;

    // ---- init ----
    {
        float* hflat = &g_h[0][0][0][0];
        float* cflat = &g_c[0][0][0];
        for (int i = cta * NT + tid; i < L_DIM * B_DIM * W_DIM; i += NB * NT) {
            hflat[i] = h0[i];
            cflat[i] = c0[i];
        }
    }
    if (cta == 0 && tid == 0) {
        const unsigned char* rb = (const unsigned char*)resets_raw;
        int s1 = 0, s2 = 0, s3 = 0;
        for (int i = 0; i < T_STEPS * B_DIM; i += 4) {
            s1 += rb[i + 1]; s2 += rb[i + 2]; s3 += rb[i + 3];
        }
        g_rmode = (s1 > 0) ? 0 : ((s2 == 0 && s3 == 0) ? 1 : 2);
    }
    gridBarrier();
    const int rmode = g_rmode;

    // ---- shared memory ----
    __shared__ __align__(16) float wsm[2][KC][68];   // 32 cols duplicated {w,w} + pad
    __shared__ __align__(16) float asmem[2][KC][36]; // 32 batches + pad
    __shared__ float gbuf[32 * 36];
    __shared__ float mask_s[B_DIM];

    // ---- thread geometry ----
    const int ks  = tid >> 6;          // 0..3  k-slice
    const int ct  = tid & 7;           // 0..7  col group (4 cols)
    const int bg  = (tid >> 3) & 7;    // 0..7  batch group (4 batches)
    const int ks8 = ks * 8;
    const int ct8 = ct * 8;            // duplicated-float offset of first col
    const int bg4 = bg * 4;
    const int u0  = cta * 8;

    // staging maps
    const int jb    = (tid & 7) * 4;                              // W: first CTA-local col
    const int kqW   = tid >> 3;                                   // W: k row 0..31
    const int gcolW = ((jb >> 3) * W_DIM) + u0 + (jb & 7);        // W: global col
    const int bA    = tid & 31;                                   // A: batch
    const int kqA   = tid >> 5;                                   // A: k quad 0..7

    // update stage map
    const int uu_up = tid & 7;
    const int b_up  = tid >> 3;

    ull* red = (ull*)&wsm[0][0][0];    // reduction scratch (reused after compute)

    for (int t = 0; t < T_STEPS; ++t) {
        const int pOld = t & 1;
        const int pNew = pOld ^ 1;

        if (tid < B_DIM) {
            int rv;
            if (rmode == 0)      rv = ((const unsigned char*)resets_raw)[t * B_DIM + tid];
            else if (rmode == 1) rv = ((const int*)resets_raw)[t * B_DIM + tid];
            else                 rv = (((const float*)resets_raw)[t * B_DIM + tid] != 0.0f);
            mask_s[tid] = rv ? 0.0f : 1.0f;
        }

        for (int l = 0; l < L_DIM; ++l) {
            const float* y    = (l == 0) ? (x + (size_t)t * B_DIM * W_DIM)
                                         : &g_h[pNew][l - 1][0][0];
            const float* hOld = &g_h[pOld][l][0][0];
            const float* wx   = Wx + (size_t)l * W_DIM * G_DIM;
            const float* wh   = Wh + (size_t)l * W_DIM * G_DIM;

            // accumulators: acc[c*2+p] = {gate(col c, b=bg4+2p), gate(col c, b=bg4+2p+1)}
            ull acc0 = 0, acc1 = 0, acc2 = 0, acc3 = 0, acc4 = 0, acc5 = 0, acc6 = 0, acc7 = 0;
            if (ks == 0) {
                #pragma unroll
                for (int c = 0; c < 4; ++c) {
                    int j = ct * 4 + c;
                    float bv = bias[l * G_DIM + (j >> 3) * W_DIM + u0 + (j & 7)];
                    unsigned bb = __float_as_uint(bv);
                    ull pr = ((ull)bb << 32) | bb;
                    if (c == 0) { acc0 = pr; acc1 = pr; }
                    else if (c == 1) { acc2 = pr; acc3 = pr; }
                    else if (c == 2) { acc4 = pr; acc5 = pr; }
                    else { acc6 = pr; acc7 = pr; }
                }
            }

            // --- prefetch + stage chunk 0 (always first half: y, no mask) ---
            float4 wv = *(const float4*)(wx + (size_t)kqW * G_DIM + gcolW);
            float4 av = *(const float4*)(y + (size_t)bA * W_DIM + kqA * 4);
            {
                float4* wd = (float4*)&wsm[0][kqW][jb * 2];
                wd[0] = make_float4(wv.x, wv.x, wv.y, wv.y);
                wd[1] = make_float4(wv.z, wv.z, wv.w, wv.w);
                asmem[0][kqA * 4 + 0][bA] = av.x;
                asmem[0][kqA * 4 + 1][bA] = av.y;
                asmem[0][kqA * 4 + 2][bA] = av.z;
                asmem[0][kqA * 4 + 3][bA] = av.w;
            }

            for (int c = 0; c < NCHUNK; ++c) {
                __syncthreads();
                const int buf = c & 1;
                const bool more = (c + 1 < NCHUNK);
                bool second = false;
                if (more) {
                    const int kc = (c + 1) * KC;
                    second = (kc >= W_DIM);
                    const float* Wb = second ? (wh + (size_t)(kc - W_DIM) * G_DIM)
                                             : (wx + (size_t)kc * G_DIM);
                    const float* Ab = second ? hOld : y;
                    const int koff = kc & (W_DIM - 1);
                    wv = *(const float4*)(Wb + (size_t)kqW * G_DIM + gcolW);
                    av = *(const float4*)(Ab + (size_t)bA * W_DIM + koff + kqA * 4);
                }

                #pragma unroll
                for (int kk = 0; kk < 8; ++kk) {
                    const int kr = ks8 + kk;
                    ulonglong2 w01 = *(const ulonglong2*)&wsm[buf][kr][ct8];
                    ulonglong2 w23 = *(const ulonglong2*)&wsm[buf][kr][ct8 + 4];
                    ulonglong2 aa  = *(const ulonglong2*)&asmem[buf][kr][bg4];
                    FFMA2(acc0, w01.x, aa.x); FFMA2(acc1, w01.x, aa.y);
                    FFMA2(acc2, w01.y, aa.x); FFMA2(acc3, w01.y, aa.y);
                    FFMA2(acc4, w23.x, aa.x); FFMA2(acc5, w23.x, aa.y);
                    FFMA2(acc6, w23.y, aa.x); FFMA2(acc7, w23.y, aa.y);
                }

                if (more) {
                    const int nb2 = (c + 1) & 1;
                    float m = second ? mask_s[bA] : 1.0f;
                    float4* wd = (float4*)&wsm[nb2][kqW][jb * 2];
                    wd[0] = make_float4(wv.x, wv.x, wv.y, wv.y);
                    wd[1] = make_float4(wv.z, wv.z, wv.w, wv.w);
                    asmem[nb2][kqA * 4 + 0][bA] = av.x * m;
                    asmem[nb2][kqA * 4 + 1][bA] = av.y * m;
                    asmem[nb2][kqA * 4 + 2][bA] = av.z * m;
                    asmem[nb2][kqA * 4 + 3][bA] = av.w * m;
                }
            }

            // --- k-slice reduction through smem (reuses wsm) ---
            __syncthreads();
            const int slot = tid & 63;
            if (ks > 0) {
                ull* r = red + ((size_t)(ks - 1) * 64 + slot) * 8;
                r[0] = acc0; r[1] = acc1; r[2] = acc2; r[3] = acc3;
                r[4] = acc4; r[5] = acc5; r[6] = acc6; r[7] = acc7;
            }
            __syncthreads();
            if (ks == 0) {
                #pragma unroll
                for (int s = 0; s < 3; ++s) {
                    ull* r = red + ((size_t)s * 64 + slot) * 8;
                    FADD2(acc0, acc0, r[0]); FADD2(acc1, acc1, r[1]);
                    FADD2(acc2, acc2, r[2]); FADD2(acc3, acc3, r[3]);
                    FADD2(acc4, acc4, r[4]); FADD2(acc5, acc5, r[5]);
                    FADD2(acc6, acc6, r[6]); FADD2(acc7, acc7, r[7]);
                }
                ull accs[8] = {acc0, acc1, acc2, acc3, acc4, acc5, acc6, acc7};
                #pragma unroll
                for (int c = 0; c < 4; ++c) {
                    int j = ct * 4 + c;
                    #pragma unroll
                    for (int p = 0; p < 2; ++p) {
                        ull v = accs[c * 2 + p];
                        gbuf[j * 36 + bg4 + 2 * p]     = __uint_as_float((unsigned)v);
                        gbuf[j * 36 + bg4 + 2 * p + 1] = __uint_as_float((unsigned)(v >> 32));
                    }
                }
            }
            __syncthreads();

            // --- pointwise LSTM update (CTA-local) ---
            {
                float gi = gbuf[(0 * 8 + uu_up) * 36 + b_up];
                float gf = gbuf[(1 * 8 + uu_up) * 36 + b_up];
                float gg = gbuf[(2 * 8 + uu_up) * 36 + b_up];
                float go = gbuf[(3 * 8 + uu_up) * 36 + b_up];
                int u = u0 + uu_up;

                float cOld = mask_s[b_up] * g_c[l][b_up][u];
                float si = 1.0f / (1.0f + expf(-gi));
                float sf = 1.0f / (1.0f + expf(-gf));
                float so = 1.0f / (1.0f + expf(-go));
                float cNew = sf * cOld + si * tanhf(gg);
                float hNew = so * tanhf(cNew);

                g_c[l][b_up][u] = cNew;
                g_h[pNew][l][b_up][u] = hNew;
                if (l == L_DIM - 1)
                    out_ys[((size_t)t * B_DIM + b_up) * W_DIM + u] = hNew;
                if (t == T_STEPS - 1) {
                    out_cs[((size_t)l * B_DIM + b_up) * W_DIM + u] = cNew;
                    out_hs[((size_t)l * B_DIM + b_up) * W_DIM + u] = hNew;
                }
            }
            gridBarrier();
        }
    }
}

extern "C" void kernel_launch(void* const* d_in, const int* in_sizes, int n_in,
                              void* d_out, int out_size) {
    const float* x      = (const float*)d_in[0];
    const void*  resets = (const void*) d_in[1];
    const float* c0     = (const float*)d_in[2];
    const float* h0     = (const float*)d_in[3];
    const float* Wx     = (const float*)d_in[4];
    const float* Wh     = (const float*)d_in[5];
    const float* b      = (const float*)d_in[6];
    (void)in_sizes; (void)n_in; (void)out_size;

    lstm_persistent_kernel<<<NB, NT>>>(x, resets, c0, h0, Wx, Wh, b, (float*)d_out);
}

// round 5
// speedup vs baseline: 6.4612x; 2.5713x over previous
#include <cuda_runtime.h>
#include <cstdint>

#define T_STEPS 64
#define B_DIM   32
#define W_DIM   1024
#define L_DIM   4
#define G_DIM   4096
#define NB      128
#define NT      256
#define KC      64
#define NCHUNK  32

__device__ float g_h [L_DIM][B_DIM][W_DIM];      // layer-forward h (same step, unmasked)
__device__ float g_hm[2][L_DIM][B_DIM][W_DIM];   // pre-masked recurrent h, by step parity
__device__ float g_c [L_DIM][B_DIM][W_DIM];      // pre-masked c
__device__ unsigned g_count = 0;
__device__ unsigned g_gen   = 0;

static __device__ __forceinline__ unsigned smem_u32(const void* p) {
    return (unsigned)__cvta_generic_to_shared(p);
}

__device__ __forceinline__ void gridBarrier() {
    __syncthreads();
    if (threadIdx.x == 0) {
        volatile unsigned* genp = &g_gen;
        unsigned my = *genp;
        __threadfence();
        unsigned arrived = atomicAdd(&g_count, 1);
        if (arrived == NB - 1) {
            atomicExch(&g_count, 0);
            __threadfence();
            *genp = my + 1;
        } else {
            while (*genp == my) { }
        }
        __threadfence();
    }
    __syncthreads();
}

__device__ __forceinline__ void cpa16(unsigned dst, const void* src) {
    asm volatile("cp.async.cg.shared.global [%0], [%1], 16;" :: "r"(dst), "l"(src));
}
__device__ __forceinline__ void cpa4(unsigned dst, const void* src) {
    asm volatile("cp.async.ca.shared.global [%0], [%1], 4;" :: "r"(dst), "l"(src));
}
#define CP_COMMIT() asm volatile("cp.async.commit_group;" ::: "memory")
#define CP_WAIT0()  asm volatile("cp.async.wait_group 0;" ::: "memory")

__device__ __forceinline__ unsigned f2tf(float f) {
    unsigned r;
    asm("cvt.rna.tf32.f32 %0, %1;" : "=r"(r) : "f"(f));
    return r;
}
__device__ __forceinline__ void mma_tf32(float& c0, float& c1, float& c2, float& c3,
                                         unsigned a0, unsigned a1, unsigned a2, unsigned a3,
                                         unsigned b0, unsigned b1) {
    asm volatile(
        "mma.sync.aligned.m16n8k8.row.col.f32.tf32.tf32.f32 "
        "{%0,%1,%2,%3}, {%4,%5,%6,%7}, {%8,%9}, {%0,%1,%2,%3};"
        : "+f"(c0), "+f"(c1), "+f"(c2), "+f"(c3)
        : "r"(a0), "r"(a1), "r"(a2), "r"(a3), "r"(b0), "r"(b1));
}

__device__ __forceinline__ float sigmoidf_(float v) { return 1.0f / (1.0f + expf(-v)); }

// smem pool layout (floats):
//   A(buf,k,m) = pool[buf*2560 + k*40 + m]          (2 x 64 x 40)
//   B(buf,k,n) = pool[5120 + buf*2560 + k*40 + n]   (2 x 64 x 40)
//   RED(w,m,n) = pool[w*1152 + m*36 + n]            (8 x 32 x 36, aliases A/B)
#define POOL_FLOATS (4 * 64 * 40)
#define A_IDX(buf, k, m) ((buf) * 2560 + (k) * 40 + (m))
#define B_IDX(buf, k, n) (5120 + (buf) * 2560 + (k) * 40 + (n))
#define RED_IDX(w, m, n) ((w) * 1152 + (m) * 36 + (n))

__global__ __launch_bounds__(NT) void lstm_mma_kernel(
    const float* __restrict__ x,
    const void*  __restrict__ resets_raw,
    const float* __restrict__ c0,
    const float* __restrict__ h0,
    const float* __restrict__ Wx,
    const float* __restrict__ Wh,
    const float* __restrict__ bias,
    float* __restrict__ out)
{
    __shared__ __align__(16) float pool[POOL_FLOATS];
    __shared__ float mask_next[B_DIM];
    __shared__ int s_rmode;

    const int tid  = threadIdx.x;
    const int cta  = blockIdx.x;
    const int lane = tid & 31;
    const int w    = tid >> 5;        // warp id 0..7 (k-slice)
    const int u0   = cta * 8;         // 8 units per CTA

    float* out_ys = out;
    float* out_cs = out + (size_t)T_STEPS * B_DIM * W_DIM;
    float* out_hs = out_cs + (size_t)L_DIM * B_DIM * W_DIM;

    if (tid == 0) {
        const unsigned char* rb = (const unsigned char*)resets_raw;
        int s1 = 0, s2 = 0, s3 = 0;
        for (int i = 0; i < T_STEPS * B_DIM; i += 4) { s1 += rb[i+1]; s2 += rb[i+2]; s3 += rb[i+3]; }
        s_rmode = (s1 > 0) ? 0 : ((s2 == 0 && s3 == 0) ? 1 : 2);
    }
    __syncthreads();
    const int rmode = s_rmode;

    const unsigned char* r8  = (const unsigned char*)resets_raw;
    const int*           r32 = (const int*)resets_raw;
    const float*         rf  = (const float*)resets_raw;
    #define KEEP(t, b) (rmode == 0 ? (r8[(t)*B_DIM+(b)] ? 0.0f : 1.0f) \
                      : rmode == 1 ? (r32[(t)*B_DIM+(b)] ? 0.0f : 1.0f) \
                                   : (rf[(t)*B_DIM+(b)] != 0.0f ? 0.0f : 1.0f))

    // ---- init state (pre-masked with keep[0]) ----
    for (int i = cta * NT + tid; i < L_DIM * B_DIM * W_DIM; i += NB * NT) {
        int b = (i >> 10) & 31;
        float k0f = KEEP(0, b);
        g_hm[0][0][0][i] = k0f * h0[i];
        g_c[0][0][i]     = k0f * c0[i];
    }
    gridBarrier();

    // staging destination addresses (bytes)
    const unsigned poolAddr = smem_u32(pool);

    // fragment lds indices
    const int c4 = lane & 3;          // k within k8 (0..3)
    const int r4 = lane >> 2;         // row/col group (0..7)
    const int kb = w * 8 + c4;        // this warp's k row in the 64-chunk

    for (int t = 0; t < T_STEPS; ++t) {
        if (tid < B_DIM)
            mask_next[tid] = (t + 1 < T_STEPS) ? KEEP(t + 1, tid) : 1.0f;

        for (int l = 0; l < L_DIM; ++l) {
            const float* wsrcX = Wx + (size_t)l * W_DIM * G_DIM;
            const float* wsrcH = Wh + (size_t)l * W_DIM * G_DIM;
            const float* ax = (l == 0) ? (x + (size_t)t * B_DIM * W_DIM) : &g_h[l - 1][0][0];
            const float* ah = &g_hm[t & 1][l][0][0];

            float acc[2][4][4];
            #pragma unroll
            for (int mt = 0; mt < 2; ++mt)
                #pragma unroll
                for (int nt = 0; nt < 4; ++nt)
                    #pragma unroll
                    for (int q = 0; q < 4; ++q) acc[mt][nt][q] = 0.0f;

            // ---- stage chunk 0 ----
            {
                #pragma unroll
                for (int i = 0; i < 2; ++i) {
                    int o = tid + NT * i, k = o >> 3, mg = o & 7;
                    cpa16(poolAddr + A_IDX(0, k, mg * 4) * 4,
                          wsrcX + (size_t)k * G_DIM + (mg >> 1) * W_DIM + u0 + (mg & 1) * 4);
                }
                #pragma unroll
                for (int i = 0; i < 8; ++i) {
                    int o = tid + NT * i, n = o >> 6, k = o & 63;
                    cpa4(poolAddr + B_IDX(0, k, n) * 4, ax + n * W_DIM + k);
                }
                CP_COMMIT();
            }

            for (int c = 0; c < NCHUNK; ++c) {
                CP_WAIT0();
                __syncthreads();

                if (c + 1 < NCHUNK) {
                    const int cn = c + 1, nb2 = cn & 1;
                    const int half = cn >> 4, kc = (cn & 15) * KC;
                    const float* wb = half ? wsrcH : wsrcX;
                    const float* ab = half ? ah : ax;
                    #pragma unroll
                    for (int i = 0; i < 2; ++i) {
                        int o = tid + NT * i, k = o >> 3, mg = o & 7;
                        cpa16(poolAddr + A_IDX(nb2, k, mg * 4) * 4,
                              wb + (size_t)(kc + k) * G_DIM + (mg >> 1) * W_DIM + u0 + (mg & 1) * 4);
                    }
                    #pragma unroll
                    for (int i = 0; i < 8; ++i) {
                        int o = tid + NT * i, n = o >> 6, k = o & 63;
                        cpa4(poolAddr + B_IDX(nb2, k, n) * 4, ab + n * W_DIM + kc + k);
                    }
                    CP_COMMIT();
                }

                // ---- compute chunk c ----
                const int buf = c & 1;
                unsigned af[2][4], bf[4][2];
                #pragma unroll
                for (int mt = 0; mt < 2; ++mt) {
                    af[mt][0] = f2tf(pool[A_IDX(buf, kb,     mt * 16 + r4)]);
                    af[mt][1] = f2tf(pool[A_IDX(buf, kb,     mt * 16 + r4 + 8)]);
                    af[mt][2] = f2tf(pool[A_IDX(buf, kb + 4, mt * 16 + r4)]);
                    af[mt][3] = f2tf(pool[A_IDX(buf, kb + 4, mt * 16 + r4 + 8)]);
                }
                #pragma unroll
                for (int nt = 0; nt < 4; ++nt) {
                    bf[nt][0] = f2tf(pool[B_IDX(buf, kb,     nt * 8 + r4)]);
                    bf[nt][1] = f2tf(pool[B_IDX(buf, kb + 4, nt * 8 + r4)]);
                }
                #pragma unroll
                for (int mt = 0; mt < 2; ++mt)
                    #pragma unroll
                    for (int nt = 0; nt < 4; ++nt)
                        mma_tf32(acc[mt][nt][0], acc[mt][nt][1], acc[mt][nt][2], acc[mt][nt][3],
                                 af[mt][0], af[mt][1], af[mt][2], af[mt][3],
                                 bf[nt][0], bf[nt][1]);
            }

            // ---- partial-sum exchange (red aliases pool) ----
            __syncthreads();
            #pragma unroll
            for (int mt = 0; mt < 2; ++mt)
                #pragma unroll
                for (int nt = 0; nt < 4; ++nt) {
                    float* p = &pool[RED_IDX(w, mt * 16 + r4, nt * 8 + 2 * c4)];
                    *(float2*)p             = make_float2(acc[mt][nt][0], acc[mt][nt][1]);
                    *(float2*)(p + 8 * 36)  = make_float2(acc[mt][nt][2], acc[mt][nt][3]);
                }
            __syncthreads();

            // ---- reduce + bias + LSTM pointwise ----
            {
                const int j = tid & 7;        // unit within CTA
                const int n = tid >> 3;       // batch
                const int u = u0 + j;
                float gate[4];
                #pragma unroll
                for (int g = 0; g < 4; ++g) {
                    float s = 0.0f;
                    #pragma unroll
                    for (int ww = 0; ww < 8; ++ww) s += pool[RED_IDX(ww, g * 8 + j, n)];
                    gate[g] = s + bias[l * G_DIM + g * W_DIM + u0 + j];
                }
                float cOld = g_c[l][n][u];     // pre-masked
                float cN = sigmoidf_(gate[1]) * cOld + sigmoidf_(gate[0]) * tanhf(gate[2]);
                float hN = sigmoidf_(gate[3]) * tanhf(cN);
                float keepN = mask_next[n];

                g_c[l][n][u] = keepN * cN;
                g_h[l][n][u] = hN;
                g_hm[(t + 1) & 1][l][n][u] = keepN * hN;
                if (l == L_DIM - 1)
                    out_ys[((size_t)t * B_DIM + n) * W_DIM + u] = hN;
                if (t == T_STEPS - 1) {
                    out_cs[((size_t)l * B_DIM + n) * W_DIM + u] = cN;
                    out_hs[((size_t)l * B_DIM + n) * W_DIM + u] = hN;
                }
            }
            gridBarrier();
        }
    }
    #undef KEEP
}

extern "C" void kernel_launch(void* const* d_in, const int* in_sizes, int n_in,
                              void* d_out, int out_size) {
    const float* x      = (const float*)d_in[0];
    const void*  resets = (const void*) d_in[1];
    const float* c0     = (const float*)d_in[2];
    const float* h0     = (const float*)d_in[3];
    const float* Wx     = (const float*)d_in[4];
    const float* Wh     = (const float*)d_in[5];
    const float* b      = (const float*)d_in[6];
    (void)in_sizes; (void)n_in; (void)out_size;

    lstm_mma_kernel<<<NB, NT>>>(x, resets, c0, h0, Wx, Wh, b, (float*)d_out);
}

// round 6
// speedup vs baseline: 28.7450x; 4.4489x over previous
#include <cuda_runtime.h>
#include <cuda_fp16.h>
#include <cstdint>

#define T_STEPS 64
#define B_DIM   32
#define W_DIM   1024
#define L_DIM   4
#define G_DIM   4096
#define NB      128
#define NT      256
#define KCH     128          // k per chunk
#define NCH     16           // 2048 / KCH
#define STAGES  4

// smem stage: A[32][136] half + B[32][136] half
#define ROWH    136          // 128 + 8 pad halfs
#define A_BYTES (32 * ROWH * 2)          // 8704
#define STAGE_BYTES (2 * A_BYTES)        // 17408
#define DYN_BYTES (STAGES * STAGE_BYTES) // 69632

__device__ __half g_W16[2][L_DIM][G_DIM][W_DIM];   // transposed fp16 weights (64 MB)
__device__ __half g_x16[T_STEPS][B_DIM][W_DIM];    // fp16 input (4 MB)
__device__ __half g_h16[L_DIM][B_DIM][W_DIM];      // layer-forward h (unmasked)
__device__ __half g_hm16[2][L_DIM][B_DIM][W_DIM];  // pre-masked recurrent h
__device__ float  g_c[L_DIM][B_DIM][W_DIM];        // pre-masked c (fp32)
__device__ unsigned g_count = 0;
__device__ unsigned g_gen   = 0;

static __device__ __forceinline__ unsigned smem_u32(const void* p) {
    return (unsigned)__cvta_generic_to_shared(p);
}

__device__ __forceinline__ void gridBarrier() {
    __syncthreads();
    if (threadIdx.x == 0) {
        volatile unsigned* genp = &g_gen;
        unsigned my = *genp;
        __threadfence();
        unsigned arrived = atomicAdd(&g_count, 1);
        if (arrived == NB - 1) {
            atomicExch(&g_count, 0);
            __threadfence();
            *genp = my + 1;
        } else {
            while (*genp == my) { }
        }
        __threadfence();
    }
    __syncthreads();
}

__device__ __forceinline__ void cpa16(unsigned dst, const void* src) {
    asm volatile("cp.async.cg.shared.global [%0], [%1], 16;" :: "r"(dst), "l"(src));
}
#define CP_COMMIT() asm volatile("cp.async.commit_group;" ::: "memory")

__device__ __forceinline__ void mma_f16(float& c0, float& c1, float& c2, float& c3,
                                        unsigned a0, unsigned a1, unsigned a2, unsigned a3,
                                        unsigned b0, unsigned b1) {
    asm volatile(
        "mma.sync.aligned.m16n8k16.row.col.f32.f16.f16.f32 "
        "{%0,%1,%2,%3}, {%4,%5,%6,%7}, {%8,%9}, {%0,%1,%2,%3};"
        : "+f"(c0), "+f"(c1), "+f"(c2), "+f"(c3)
        : "r"(a0), "r"(a1), "r"(a2), "r"(a3), "r"(b0), "r"(b1));
}

__device__ __forceinline__ float sigmoidf_(float v) { return 1.0f / (1.0f + expf(-v)); }

// ---------------- one-time converts ----------------
__global__ void convert_w_kernel(const float* __restrict__ Wx, const float* __restrict__ Wh) {
    __shared__ float tile[32][33];
    const int w = blockIdx.z >> 2, l = blockIdx.z & 3;
    const float* src = (w ? Wh : Wx) + (size_t)l * W_DIM * G_DIM;
    const int c0 = blockIdx.x * 32, k0 = blockIdx.y * 32;
    const int tx = threadIdx.x, ty = threadIdx.y;   // 32 x 8
    #pragma unroll
    for (int i = 0; i < 4; i++)
        tile[ty + 8 * i][tx] = src[(size_t)(k0 + ty + 8 * i) * G_DIM + c0 + tx];
    __syncthreads();
    __half* dst = &g_W16[w][l][0][0];
    #pragma unroll
    for (int i = 0; i < 4; i++)
        dst[(size_t)(c0 + ty + 8 * i) * W_DIM + k0 + tx] = __float2half(tile[tx][ty + 8 * i]);
}

__global__ void convert_x_kernel(const float* __restrict__ x) {
    __half* dst = &g_x16[0][0][0];
    int i = blockIdx.x * blockDim.x + threadIdx.x;
    #pragma unroll
    for (int r = 0; r < 8; ++r) {
        int idx = i + r * (gridDim.x * blockDim.x);
        if (idx < T_STEPS * B_DIM * W_DIM) dst[idx] = __float2half(x[idx]);
    }
}

// reduction scratch layout (aliases pool): RED[w][m][n] floats
#define RED_IDX(w, m, n) ((w) * 1152 + (m) * 36 + (n))

__global__ __launch_bounds__(NT) void lstm_mma_kernel(
    const void*  __restrict__ resets_raw,
    const float* __restrict__ c0,
    const float* __restrict__ h0,
    const float* __restrict__ bias,
    float* __restrict__ out)
{
    extern __shared__ __align__(16) char pool[];
    __shared__ float mask_next[B_DIM];
    __shared__ int s_rmode;

    const int tid  = threadIdx.x;
    const int cta  = blockIdx.x;
    const int lane = tid & 31;
    const int w    = tid >> 5;        // warp id 0..7 -> k-slice w*16
    const int u0   = cta * 8;

    float* out_ys = out;
    float* out_cs = out + (size_t)T_STEPS * B_DIM * W_DIM;
    float* out_hs = out_cs + (size_t)L_DIM * B_DIM * W_DIM;

    if (tid == 0) {
        const unsigned char* rb = (const unsigned char*)resets_raw;
        int s1 = 0, s2 = 0, s3 = 0;
        for (int i = 0; i < T_STEPS * B_DIM; i += 4) { s1 += rb[i+1]; s2 += rb[i+2]; s3 += rb[i+3]; }
        s_rmode = (s1 > 0) ? 0 : ((s2 == 0 && s3 == 0) ? 1 : 2);
    }
    __syncthreads();
    const int rmode = s_rmode;

    const unsigned char* r8  = (const unsigned char*)resets_raw;
    const int*           r32 = (const int*)resets_raw;
    const float*         rf  = (const float*)resets_raw;
    #define KEEP(t, b) (rmode == 0 ? (r8[(t)*B_DIM+(b)] ? 0.0f : 1.0f) \
                      : rmode == 1 ? (r32[(t)*B_DIM+(b)] ? 0.0f : 1.0f) \
                                   : (rf[(t)*B_DIM+(b)] != 0.0f ? 0.0f : 1.0f))

    // ---- init state (pre-masked with keep[0]) ----
    for (int i = cta * NT + tid; i < L_DIM * B_DIM * W_DIM; i += NB * NT) {
        int b = (i >> 10) & 31;
        float k0f = KEEP(0, b);
        (&g_hm16[0][0][0][0])[i] = __float2half(k0f * h0[i]);
        (&g_c[0][0][0])[i]       = k0f * c0[i];
    }
    gridBarrier();

    // ---- staging constants ----
    const unsigned poolAddr = smem_u32(pool);
    const int m0  = tid >> 4;          // 0..15 (row for i=0; +16 for i=1)
    const int kq8 = (tid & 15) * 8;    // half offset within 128-k row
    const size_t wOff0 = (size_t)(((m0      ) >> 3) * W_DIM + u0 + (m0 & 7))        * W_DIM;
    const size_t wOff1 = (size_t)(((m0 + 16 ) >> 3) * W_DIM + u0 + ((m0 + 16) & 7)) * W_DIM;
    const unsigned aD0 = (unsigned)((m0 * ROWH + kq8) * 2);
    const unsigned aD1 = (unsigned)(((m0 + 16) * ROWH + kq8) * 2);
    const size_t actOff0 = (size_t)m0 * W_DIM;
    const size_t actOff1 = (size_t)(m0 + 16) * W_DIM;

    const int row = lane >> 2;         // 0..7
    const int kc2 = (lane & 3) * 2;    // 0,2,4,6
    const int kb  = w * 16;            // warp k-slice base in chunk

    for (int t = 0; t < T_STEPS; ++t) {
        if (tid < B_DIM)
            mask_next[tid] = (t + 1 < T_STEPS) ? KEEP(t + 1, tid) : 1.0f;

        for (int l = 0; l < L_DIM; ++l) {
            const __half* wX = &g_W16[0][l][0][0];
            const __half* wH = &g_W16[1][l][0][0];
            const __half* ax = (l == 0) ? &g_x16[t][0][0] : &g_h16[l - 1][0][0];
            const __half* ah = &g_hm16[t & 1][l][0][0];

            float acc[2][4][4];
            #pragma unroll
            for (int mt = 0; mt < 2; ++mt)
                #pragma unroll
                for (int nt = 0; nt < 4; ++nt)
                    #pragma unroll
                    for (int q = 0; q < 4; ++q) acc[mt][nt][q] = 0.0f;

            // ---- prologue: stage chunks 0..2 ----
            #pragma unroll
            for (int c = 0; c < STAGES - 1; ++c) {
                const int half = c >> 3, kc = (c & 7) * KCH;
                const __half* wb = half ? wH : wX;
                const __half* ab = half ? ah : ax;
                const unsigned base = poolAddr + c * STAGE_BYTES;
                cpa16(base + aD0, wb + wOff0 + kc + kq8);
                cpa16(base + aD1, wb + wOff1 + kc + kq8);
                cpa16(base + A_BYTES + aD0, ab + actOff0 + kc + kq8);
                cpa16(base + A_BYTES + aD1, ab + actOff1 + kc + kq8);
                CP_COMMIT();
            }

            for (int c = 0; c < NCH; ++c) {
                __syncthreads();   // all warps done with chunk c-1 (stage being overwritten)
                if (c + STAGES - 1 < NCH) {
                    const int cn = c + STAGES - 1;
                    const int half = cn >> 3, kc = (cn & 7) * KCH;
                    const __half* wb = half ? wH : wX;
                    const __half* ab = half ? ah : ax;
                    const unsigned base = poolAddr + (cn & (STAGES - 1)) * STAGE_BYTES;
                    cpa16(base + aD0, wb + wOff0 + kc + kq8);
                    cpa16(base + aD1, wb + wOff1 + kc + kq8);
                    cpa16(base + A_BYTES + aD0, ab + actOff0 + kc + kq8);
                    cpa16(base + A_BYTES + aD1, ab + actOff1 + kc + kq8);
                    CP_COMMIT();
                }
                // wait until group for chunk c complete (tail-aware)
                if (c + STAGES - 1 < NCH)      asm volatile("cp.async.wait_group 3;" ::: "memory");
                else if (c + STAGES - 2 < NCH) asm volatile("cp.async.wait_group 2;" ::: "memory");
                else if (c + STAGES - 3 < NCH) asm volatile("cp.async.wait_group 1;" ::: "memory");
                else                           asm volatile("cp.async.wait_group 0;" ::: "memory");
                __syncthreads();   // everyone's copies visible

                // ---- compute chunk c ----
                const char* As = pool + (c & (STAGES - 1)) * STAGE_BYTES;
                const char* Bs = As + A_BYTES;
                unsigned af[2][4], bf[4][2];
                #pragma unroll
                for (int mt = 0; mt < 2; ++mt) {
                    const int mr = mt * 16 + row;
                    af[mt][0] = *(const unsigned*)(As + ((mr    ) * ROWH + kb + kc2) * 2);
                    af[mt][1] = *(const unsigned*)(As + ((mr + 8) * ROWH + kb + kc2) * 2);
                    af[mt][2] = *(const unsigned*)(As + ((mr    ) * ROWH + kb + kc2 + 8) * 2);
                    af[mt][3] = *(const unsigned*)(As + ((mr + 8) * ROWH + kb + kc2 + 8) * 2);
                }
                #pragma unroll
                for (int nt = 0; nt < 4; ++nt) {
                    const int nr = nt * 8 + row;
                    bf[nt][0] = *(const unsigned*)(Bs + (nr * ROWH + kb + kc2) * 2);
                    bf[nt][1] = *(const unsigned*)(Bs + (nr * ROWH + kb + kc2 + 8) * 2);
                }
                #pragma unroll
                for (int mt = 0; mt < 2; ++mt)
                    #pragma unroll
                    for (int nt = 0; nt < 4; ++nt)
                        mma_f16(acc[mt][nt][0], acc[mt][nt][1], acc[mt][nt][2], acc[mt][nt][3],
                                af[mt][0], af[mt][1], af[mt][2], af[mt][3],
                                bf[nt][0], bf[nt][1]);
            }

            // ---- partial-sum exchange (aliases pool) ----
            __syncthreads();
            float* red = (float*)pool;
            #pragma unroll
            for (int mt = 0; mt < 2; ++mt)
                #pragma unroll
                for (int nt = 0; nt < 4; ++nt) {
                    float* p = &red[RED_IDX(w, mt * 16 + row, nt * 8 + kc2)];
                    *(float2*)p            = make_float2(acc[mt][nt][0], acc[mt][nt][1]);
                    *(float2*)(p + 8 * 36) = make_float2(acc[mt][nt][2], acc[mt][nt][3]);
                }
            __syncthreads();

            // ---- reduce + bias + LSTM pointwise ----
            {
                const int j = tid & 7;
                const int n = tid >> 3;
                const int u = u0 + j;
                float gate[4];
                #pragma unroll
                for (int g = 0; g < 4; ++g) {
                    float s = 0.0f;
                    #pragma unroll
                    for (int ww = 0; ww < 8; ++ww) s += red[RED_IDX(ww, g * 8 + j, n)];
                    gate[g] = s + bias[l * G_DIM + g * W_DIM + u0 + j];
                }
                float cOld = g_c[l][n][u];
                float cN = sigmoidf_(gate[1]) * cOld + sigmoidf_(gate[0]) * tanhf(gate[2]);
                float hN = sigmoidf_(gate[3]) * tanhf(cN);
                float keepN = mask_next[n];

                g_c[l][n][u]   = keepN * cN;
                g_h16[l][n][u] = __float2half(hN);
                g_hm16[(t + 1) & 1][l][n][u] = __float2half(keepN * hN);
                if (l == L_DIM - 1)
                    out_ys[((size_t)t * B_DIM + n) * W_DIM + u] = hN;
                if (t == T_STEPS - 1) {
                    out_cs[((size_t)l * B_DIM + n) * W_DIM + u] = cN;
                    out_hs[((size_t)l * B_DIM + n) * W_DIM + u] = hN;
                }
            }
            gridBarrier();
        }
    }
    #undef KEEP
}

extern "C" void kernel_launch(void* const* d_in, const int* in_sizes, int n_in,
                              void* d_out, int out_size) {
    const float* x      = (const float*)d_in[0];
    const void*  resets = (const void*) d_in[1];
    const float* c0     = (const float*)d_in[2];
    const float* h0     = (const float*)d_in[3];
    const float* Wx     = (const float*)d_in[4];
    const float* Wh     = (const float*)d_in[5];
    const float* b      = (const float*)d_in[6];
    (void)in_sizes; (void)n_in; (void)out_size;

    static int configured = 0;
    if (!configured) {
        cudaFuncSetAttribute(lstm_mma_kernel, cudaFuncAttributeMaxDynamicSharedMemorySize, DYN_BYTES);
        configured = 1;
    }

    convert_w_kernel<<<dim3(G_DIM / 32, W_DIM / 32, 8), dim3(32, 8)>>>(Wx, Wh);
    convert_x_kernel<<<1024, 256>>>(x);
    lstm_mma_kernel<<<NB, NT, DYN_BYTES>>>(resets, c0, h0, b, (float*)d_out);
}